// round 15
// baseline (speedup 1.0000x reference)
#include <cuda_runtime.h>
#include <cuda_fp16.h>
#include <mma.h>
#include <math.h>

using namespace nvcuda;

#define NN 100000
#define NE 3200000
// 3-chunk cascade: boundaries must be multiples of 64 (gemmT row0)
#define C0 50048
#define C1 29952              // C0+C1 = 80000 (x64 ok)
#define C2 20000              // tail

#define PAD 72                 // half stride for wmma smem tiles
#define OPAD 68                // float stride for epilogue buffers
#define SM_HALVES (7*64*PAD)
#define SMEM_T (SM_HALVES*2)   // 64512 bytes

// ---------------- scratch (device globals) ----------------
__device__ __align__(16) uint2 g_qh[2*NN*16];    // q fp16: per node,lane {q0..3}
__device__ __align__(16) uint4 g_kvh[2*NN*16];   // per node,lane: {k0..3,v0..3} fp16
__device__ __align__(16) float g_s [2*NN*64];
__device__ __align__(16) float g_h [NN*64];
__device__ __align__(16) float g_q3 [NN*4];
__device__ __align__(16) float g_s3 [NN*4];
__device__ __align__(32) float g_kv3[NN*8];
__device__ int g_deg[NN];
__device__ int g_ptr[NN+1];
__device__ int g_rank[NE];
__device__ int g_esrc[NE];

// ---------------- CSR build ----------------
__global__ void hist_k(const int* __restrict__ ei){
    int i = blockIdx.x*blockDim.x + threadIdx.x;
    if (i < NE/4){
        int4 d = ((const int4*)(ei + NE))[i];
        int4 r;
        r.x = atomicAdd(&g_deg[d.x], 1);
        r.y = atomicAdd(&g_deg[d.y], 1);
        r.z = atomicAdd(&g_deg[d.z], 1);
        r.w = atomicAdd(&g_deg[d.w], 1);
        ((int4*)g_rank)[i] = r;
    }
}
__global__ void __launch_bounds__(1024) scan_k(){
    __shared__ int sh[1024];
    int t = threadIdx.x;
    int carry = 0;
    for (int base = 0; base < NN; base += 4096){
        int v[4]; int s = 0;
        #pragma unroll
        for (int j = 0; j < 4; j++){
            int idx = base + t*4 + j;
            v[j] = (idx < NN) ? g_deg[idx] : 0;
            s += v[j];
        }
        sh[t] = s; __syncthreads();
        #pragma unroll
        for (int off = 1; off < 1024; off <<= 1){
            int x = (t >= off) ? sh[t-off] : 0;
            __syncthreads();
            sh[t] += x;
            __syncthreads();
        }
        int total = sh[1023];
        int excl = carry + sh[t] - s;
        #pragma unroll
        for (int j = 0; j < 4; j++){
            int idx = base + t*4 + j;
            if (idx < NN) g_ptr[idx] = excl;
            excl += v[j];
        }
        carry += total;
        __syncthreads();
    }
    if (t == 0) g_ptr[NN] = carry;
}
__global__ void scatter_k(const int* __restrict__ ei){
    int i = blockIdx.x*blockDim.x + threadIdx.x;
    if (i < NE/4){
        int4 s = ((const int4*)ei)[i];
        int4 d = ((const int4*)(ei + NE))[i];
        int4 r = ((const int4*)g_rank)[i];
        g_esrc[g_ptr[d.x] + r.x] = s.x;
        g_esrc[g_ptr[d.y] + r.y] = s.y;
        g_esrc[g_ptr[d.z] + r.z] = s.z;
        g_esrc[g_ptr[d.w] + r.w] = s.w;
    }
}

// ---------------- tensor-core quad GEMM, vectorized staging -----------------
__global__ void __launch_bounds__(256) gemmT(
    const float* __restrict__ X,
    const float* __restrict__ Wq, const float* __restrict__ bq,
    const float* __restrict__ Wk, const float* __restrict__ bk,
    const float* __restrict__ Wv, const float* __restrict__ bv,
    const float* __restrict__ Ws, const float* __restrict__ bs,
    int row0, int buf, int addres)
{
    extern __shared__ __half sm[];
    __half* Ah  = sm;
    __half* Al  = sm + 64*PAD;
    __half* Bq  = sm + 2*64*PAD;
    __half* Bk  = sm + 3*64*PAD;
    __half* Bv  = sm + 4*64*PAD;
    __half* Bsh = sm + 5*64*PAD;
    __half* Bsl = sm + 6*64*PAD;

    int t   = threadIdx.x;
    int r0  = row0 + blockIdx.x*64;
    int wid = t >> 5;
    int grp = wid >> 2;
    int rt  = wid & 3;

    uint2* QH = g_qh + (size_t)buf*NN*16;
    float* S  = g_s  + (size_t)buf*NN*64;
    uint4* KV = g_kvh + (size_t)buf*NN*16;

    // ---- stage X (split hi/lo), STS.64 ----
    #pragma unroll
    for (int i = 0; i < 4; i++){
        int s = t + i*256;
        int row = s >> 4, c0 = (s & 15)*4;
        float4 xv = make_float4(0.f,0.f,0.f,0.f);
        if (r0 + row < NN) xv = ((const float4*)X)[(size_t)(r0+row)*16 + (c0>>2)];
        __half2 h0 = __floats2half2_rn(xv.x, xv.y);
        __half2 h1 = __floats2half2_rn(xv.z, xv.w);
        float2 f0 = __half22float2(h0), f1 = __half22float2(h1);
        __half2 l0 = __floats2half2_rn(xv.x - f0.x, xv.y - f0.y);
        __half2 l1 = __floats2half2_rn(xv.z - f1.x, xv.w - f1.y);
        uint2 uh, ul;
        *(__half2*)&uh.x = h0; *(__half2*)&uh.y = h1;
        *(__half2*)&ul.x = l0; *(__half2*)&ul.y = l1;
        *(uint2*)&Ah[row*PAD + c0] = uh;
        *(uint2*)&Al[row*PAD + c0] = ul;
    }
    // ---- stage weights, STS.128 ----
    #pragma unroll
    for (int i = 0; i < 2; i++){
        int ch = t + i*256;
        int k = ch >> 3, c0 = (ch & 7)*8;
        int q4 = k*16 + (c0>>2);
        float4 a, b; uint4 u;
        a = ((const float4*)Wq)[q4]; b = ((const float4*)Wq)[q4+1];
        *(__half2*)&u.x = __floats2half2_rn(a.x,a.y);
        *(__half2*)&u.y = __floats2half2_rn(a.z,a.w);
        *(__half2*)&u.z = __floats2half2_rn(b.x,b.y);
        *(__half2*)&u.w = __floats2half2_rn(b.z,b.w);
        *(uint4*)&Bq[k*PAD + c0] = u;
        a = ((const float4*)Wk)[q4]; b = ((const float4*)Wk)[q4+1];
        *(__half2*)&u.x = __floats2half2_rn(a.x,a.y);
        *(__half2*)&u.y = __floats2half2_rn(a.z,a.w);
        *(__half2*)&u.z = __floats2half2_rn(b.x,b.y);
        *(__half2*)&u.w = __floats2half2_rn(b.z,b.w);
        *(uint4*)&Bk[k*PAD + c0] = u;
        a = ((const float4*)Wv)[q4]; b = ((const float4*)Wv)[q4+1];
        *(__half2*)&u.x = __floats2half2_rn(a.x,a.y);
        *(__half2*)&u.y = __floats2half2_rn(a.z,a.w);
        *(__half2*)&u.z = __floats2half2_rn(b.x,b.y);
        *(__half2*)&u.w = __floats2half2_rn(b.z,b.w);
        *(uint4*)&Bv[k*PAD + c0] = u;
        a = ((const float4*)Ws)[q4]; b = ((const float4*)Ws)[q4+1];
        __half2 h0 = __floats2half2_rn(a.x,a.y);
        __half2 h1 = __floats2half2_rn(a.z,a.w);
        __half2 h2 = __floats2half2_rn(b.x,b.y);
        __half2 h3 = __floats2half2_rn(b.z,b.w);
        *(__half2*)&u.x = h0; *(__half2*)&u.y = h1;
        *(__half2*)&u.z = h2; *(__half2*)&u.w = h3;
        *(uint4*)&Bsh[k*PAD + c0] = u;
        float2 g0 = __half22float2(h0), g1 = __half22float2(h1);
        float2 g2 = __half22float2(h2), g3 = __half22float2(h3);
        *(__half2*)&u.x = __floats2half2_rn(a.x-g0.x, a.y-g0.y);
        *(__half2*)&u.y = __floats2half2_rn(a.z-g1.x, a.w-g1.y);
        *(__half2*)&u.z = __floats2half2_rn(b.x-g2.x, b.y-g2.y);
        *(__half2*)&u.w = __floats2half2_rn(b.z-g3.x, b.w-g3.y);
        *(uint4*)&Bsl[k*PAD + c0] = u;
    }
    __syncthreads();

    wmma::fragment<wmma::accumulator, 16,16,16, float> acc[8];
    #pragma unroll
    for (int i = 0; i < 8; i++) wmma::fill_fragment(acc[i], 0.f);

    #pragma unroll
    for (int kk = 0; kk < 4; kk++){
        int ka = kk*16;
        wmma::fragment<wmma::matrix_a, 16,16,16, __half, wmma::row_major> ah, al;
        wmma::load_matrix_sync(ah, Ah + rt*16*PAD + ka, PAD);
        wmma::load_matrix_sync(al, Al + rt*16*PAD + ka, PAD);
        wmma::fragment<wmma::matrix_b, 16,16,16, __half, wmma::row_major> b;
        if (grp == 0){
            #pragma unroll
            for (int ct = 0; ct < 4; ct++){
                wmma::load_matrix_sync(b, Bq + ka*PAD + ct*16, PAD);
                wmma::mma_sync(acc[ct], ah, b, acc[ct]);
                wmma::mma_sync(acc[ct], al, b, acc[ct]);
            }
            #pragma unroll
            for (int ct = 0; ct < 4; ct++){
                wmma::load_matrix_sync(b, Bk + ka*PAD + ct*16, PAD);
                wmma::mma_sync(acc[4+ct], ah, b, acc[4+ct]);
                wmma::mma_sync(acc[4+ct], al, b, acc[4+ct]);
            }
        } else {
            #pragma unroll
            for (int ct = 0; ct < 4; ct++){
                wmma::load_matrix_sync(b, Bv + ka*PAD + ct*16, PAD);
                wmma::mma_sync(acc[ct], ah, b, acc[ct]);
            }
            #pragma unroll
            for (int ct = 0; ct < 4; ct++){
                wmma::load_matrix_sync(b, Bsh + ka*PAD + ct*16, PAD);
                wmma::mma_sync(acc[4+ct], ah, b, acc[4+ct]);
                wmma::mma_sync(acc[4+ct], al, b, acc[4+ct]);
                wmma::load_matrix_sync(b, Bsl + ka*PAD + ct*16, PAD);
                wmma::mma_sync(acc[4+ct], ah, b, acc[4+ct]);
            }
        }
    }
    __syncthreads();

    float* obuf0 = (float*)sm;
    float* obuf1 = (float*)sm + 64*OPAD;
    bool res = (addres != 0);

    // ---- round A: Q (fp16) + V ----
    {
        float* dst = (grp == 0) ? obuf0 : obuf1;
        #pragma unroll
        for (int ct = 0; ct < 4; ct++)
            wmma::store_matrix_sync(dst + rt*16*OPAD + ct*16, acc[ct], OPAD,
                                    wmma::mem_row_major);
    }
    __syncthreads();
    #pragma unroll
    for (int i = 0; i < 4; i++){
        int e = t + i*256;
        int row = e >> 4, c4 = e & 15;
        if (r0 + row < NN){
            size_t grow = (size_t)(r0+row);
            const float* sq = obuf0 + row*OPAD + c4*4;
            float4 bqv = ((const float4*)bq)[c4];
            __half2 q0 = __floats2half2_rn(sq[0]+bqv.x, sq[1]+bqv.y);
            __half2 q1 = __floats2half2_rn(sq[2]+bqv.z, sq[3]+bqv.w);
            uint2 uq; *(__half2*)&uq.x = q0; *(__half2*)&uq.y = q1;
            QH[grow*16 + c4] = uq;
            const float* sv = obuf1 + row*OPAD + c4*4;
            float4 bvv = ((const float4*)bv)[c4];
            __half2 h0 = __floats2half2_rn(sv[0]+bvv.x, sv[1]+bvv.y);
            __half2 h1 = __floats2half2_rn(sv[2]+bvv.z, sv[3]+bvv.w);
            uint2 u; *(__half2*)&u.x = h0; *(__half2*)&u.y = h1;
            ((uint2*)&KV[grow*16 + c4])[1] = u;
        }
    }
    __syncthreads();

    // ---- round B: K + S ----
    {
        float* dst = (grp == 0) ? obuf0 : obuf1;
        #pragma unroll
        for (int ct = 0; ct < 4; ct++)
            wmma::store_matrix_sync(dst + rt*16*OPAD + ct*16, acc[4+ct], OPAD,
                                    wmma::mem_row_major);
    }
    __syncthreads();
    #pragma unroll
    for (int i = 0; i < 4; i++){
        int e = t + i*256;
        int row = e >> 4, c4 = e & 15;
        if (r0 + row < NN){
            size_t grow = (size_t)(r0+row);
            const float* sk_ = obuf0 + row*OPAD + c4*4;
            float4 bkv = ((const float4*)bk)[c4];
            __half2 h0 = __floats2half2_rn(sk_[0]+bkv.x, sk_[1]+bkv.y);
            __half2 h1 = __floats2half2_rn(sk_[2]+bkv.z, sk_[3]+bkv.w);
            uint2 u; *(__half2*)&u.x = h0; *(__half2*)&u.y = h1;
            ((uint2*)&KV[grow*16 + c4])[0] = u;
            const float* ss = obuf1 + row*OPAD + c4*4;
            float4 bsv = ((const float4*)bs)[c4];
            float4 os = make_float4(ss[0]+bsv.x, ss[1]+bsv.y,
                                    ss[2]+bsv.z, ss[3]+bsv.w);
            if (res){
                float4 xv = ((const float4*)X)[grow*16 + c4];
                os.x += xv.x; os.y += xv.y; os.z += xv.z; os.w += xv.w;
            }
            ((float4*)S)[grow*16 + c4] = os;
        }
    }
}

// ------- fused per-node attention, D=64: one node/warp, fp16 q, HFMA2 dots --
__device__ __forceinline__ float dot4hh(__half2 q01, __half2 q23,
                                        unsigned a, unsigned b){
    __half2 p = __hmul2(q01, *(__half2*)&a);
    p = __hfma2(q23, *(__half2*)&b, p);
    float2 f = __half22float2(p);
    return f.x + f.y;
}
__device__ __forceinline__ void accv(float4& acc, float e, unsigned a, unsigned b){
    float2 f01 = __half22float2(*(__half2*)&a);
    float2 f23 = __half22float2(*(__half2*)&b);
    acc.x += e*f01.x; acc.y += e*f01.y; acc.z += e*f23.x; acc.w += e*f23.y;
}

__global__ void __launch_bounds__(256) edge64(int buf, int base, int nnodes){
    int lid = blockIdx.x*8 + (threadIdx.x >> 5);
    if (lid >= nnodes) return;
    int gid = base + lid;
    int lane = threadIdx.x & 15;
    int half = (threadIdx.x >> 4) & 1;
    unsigned gmask = 0xffffu << (threadIdx.x & 16);

    const uint2* QH = g_qh + (size_t)buf*NN*16;
    const float* S  = g_s  + (size_t)buf*NN*64;
    const uint4* KV = g_kvh + (size_t)buf*NN*16;

    uint2 qr = QH[(size_t)gid*16 + lane];
    __half2 q01 = *(__half2*)&qr.x;
    __half2 q23 = *(__half2*)&qr.y;
    int beg = g_ptr[gid], end = g_ptr[gid+1];

    float4 acc = make_float4(0.f,0.f,0.f,0.f);
    float ssum = 0.f;

    for (int i = beg + half*4; i + 4 <= end; i += 8){
        int s0 = g_esrc[i],   s1 = g_esrc[i+1];
        int s2 = g_esrc[i+2], s3 = g_esrc[i+3];
        uint4 kv0 = KV[(size_t)s0*16 + lane];
        uint4 kv1 = KV[(size_t)s1*16 + lane];
        uint4 kv2 = KV[(size_t)s2*16 + lane];
        uint4 kv3 = KV[(size_t)s3*16 + lane];
        float d0 = dot4hh(q01, q23, kv0.x, kv0.y);
        float d1 = dot4hh(q01, q23, kv1.x, kv1.y);
        float d2 = dot4hh(q01, q23, kv2.x, kv2.y);
        float d3 = dot4hh(q01, q23, kv3.x, kv3.y);
        #pragma unroll
        for (int o = 8; o >= 1; o >>= 1){
            d0 += __shfl_xor_sync(gmask, d0, o);
            d1 += __shfl_xor_sync(gmask, d1, o);
            d2 += __shfl_xor_sync(gmask, d2, o);
            d3 += __shfl_xor_sync(gmask, d3, o);
        }
        float e0 = __expf(d0*0.125f);
        float e1 = __expf(d1*0.125f);
        float e2 = __expf(d2*0.125f);
        float e3 = __expf(d3*0.125f);
        ssum += (e0 + e1) + (e2 + e3);
        accv(acc, e0, kv0.z, kv0.w); accv(acc, e1, kv1.z, kv1.w);
        accv(acc, e2, kv2.z, kv2.w); accv(acc, e3, kv3.z, kv3.w);
    }
    if (half == 0){
        for (int i = beg + ((end - beg) & ~3); i < end; i++){
            int s0 = g_esrc[i];
            uint4 kv0 = KV[(size_t)s0*16 + lane];
            float d0 = dot4hh(q01, q23, kv0.x, kv0.y);
            #pragma unroll
            for (int o = 8; o >= 1; o >>= 1)
                d0 += __shfl_xor_sync(gmask, d0, o);
            float e0 = __expf(d0*0.125f);
            ssum += e0;
            accv(acc, e0, kv0.z, kv0.w);
        }
    }
    ssum  += __shfl_xor_sync(0xffffffffu, ssum,  16);
    acc.x += __shfl_xor_sync(0xffffffffu, acc.x, 16);
    acc.y += __shfl_xor_sync(0xffffffffu, acc.y, 16);
    acc.z += __shfl_xor_sync(0xffffffffu, acc.z, 16);
    acc.w += __shfl_xor_sync(0xffffffffu, acc.w, 16);

    float inv = 1.0f / (ssum + 1e-16f);
    float4 sk = ((const float4*)S)[(size_t)gid*16 + lane];
    float4 o;
    o.x = tanhf(acc.x*inv + sk.x);
    o.y = tanhf(acc.y*inv + sk.y);
    o.z = tanhf(acc.z*inv + sk.z);
    o.w = tanhf(acc.w*inv + sk.w);
    if (half == 0)
        ((float4*)g_h)[(size_t)gid*16 + lane] = o;
}

// ---------------- layer 3: 64 -> (3 x 4) GEMM over row range ----------------
__global__ void __launch_bounds__(256) gemm3(
    const float* __restrict__ X,
    const float* __restrict__ Wq, const float* __restrict__ bq,
    const float* __restrict__ Wk, const float* __restrict__ bk,
    const float* __restrict__ Wv, const float* __restrict__ bv,
    const float* __restrict__ Ws, const float* __restrict__ bs,
    const float* __restrict__ noise, int row0, int nrows)
{
    __shared__ float w[64*12];
    __shared__ float bias[12];
    int t = threadIdx.x;
    if (t < 192){
        int kk = t/3, j = t%3;
        w[kk*12 + 0 + j] = Wq[t];
        w[kk*12 + 3 + j] = Wk[t];
        w[kk*12 + 6 + j] = Wv[t];
        w[kk*12 + 9 + j] = Ws[t];
    }
    if (t < 3){
        bias[t]   = bq[t];
        bias[3+t] = bk[t];
        bias[6+t] = bv[t];
        bias[9+t] = bs[t];
    }
    __syncthreads();
    int node = row0 + blockIdx.x*256 + t;
    if (node >= row0 + nrows || node >= NN) return;
    float acc[12];
    #pragma unroll
    for (int j = 0; j < 12; j++) acc[j] = 0.f;
    #pragma unroll
    for (int kk = 0; kk < 16; kk++){
        float4 xv = ((const float4*)X)[(size_t)node*16 + kk];
        #pragma unroll
        for (int j = 0; j < 12; j++){
            acc[j] += xv.x * w[(kk*4+0)*12+j]
                    + xv.y * w[(kk*4+1)*12+j]
                    + xv.z * w[(kk*4+2)*12+j]
                    + xv.w * w[(kk*4+3)*12+j];
        }
    }
    float4 q3 = make_float4(acc[0]+bias[0], acc[1]+bias[1], acc[2]+bias[2], 0.f);
    float4 kva = make_float4(acc[3]+bias[3], acc[4]+bias[4], acc[5]+bias[5],
                             acc[6]+bias[6]);
    float4 kvb = make_float4(acc[7]+bias[7], acc[8]+bias[8], 0.f, 0.f);
    float4 s3 = make_float4(acc[9]+bias[9]   + 0.1f*noise[node*3+0],
                            acc[10]+bias[10] + 0.1f*noise[node*3+1],
                            acc[11]+bias[11] + 0.1f*noise[node*3+2], 0.f);
    ((float4*)g_q3)[node] = q3;
    ((float4*)g_kv3)[node*2]   = kva;
    ((float4*)g_kv3)[node*2+1] = kvb;
    ((float4*)g_s3)[node] = s3;
}

// ------- layer-3 per-node attention: 8 lanes per node -------
__global__ void __launch_bounds__(256) edge3(float* __restrict__ out){
    int nid = blockIdx.x*32 + (threadIdx.x >> 3);
    if (nid >= NN) return;
    int lane = threadIdx.x & 7;
    unsigned gmask = 0xFFu << (threadIdx.x & 24);

    float4 q = ((const float4*)g_q3)[nid];
    int beg = g_ptr[nid], end = g_ptr[nid+1];
    float sum = 0.f, ax = 0.f, ay = 0.f, az = 0.f;
    for (int i = beg + lane; i < end; i += 8){
        int s0 = g_esrc[i];
        float4 a0 = ((const float4*)g_kv3)[s0*2];
        float4 b0 = ((const float4*)g_kv3)[s0*2+1];
        float e0 = __expf((q.x*a0.x + q.y*a0.y + q.z*a0.z)*0.57735026919f);
        sum += e0;
        ax += e0*a0.w; ay += e0*b0.x; az += e0*b0.y;
    }
    #pragma unroll
    for (int o = 4; o >= 1; o >>= 1){
        sum += __shfl_xor_sync(gmask, sum, o);
        ax  += __shfl_xor_sync(gmask, ax,  o);
        ay  += __shfl_xor_sync(gmask, ay,  o);
        az  += __shfl_xor_sync(gmask, az,  o);
    }
    if (lane == 0){
        float inv = 1.0f / (sum + 1e-16f);
        float4 s3 = ((const float4*)g_s3)[nid];
        out[nid*3+0] = ax*inv + s3.x;
        out[nid*3+1] = ay*inv + s3.y;
        out[nid*3+2] = az*inv + s3.z;
    }
}

// ---------------- launcher: 3-chunk cascaded pipeline ----------------
extern "C" void kernel_launch(void* const* d_in, const int* in_sizes, int n_in,
                              void* d_out, int out_size)
{
    const float* x     = (const float*)d_in[0];
    const int*   ei    = (const int*)d_in[1];
    const float* noise = (const float*)d_in[2];
    const float* p[24];
    for (int i = 0; i < 24; i++) p[i] = (const float*)d_in[3+i];
    float* out = (float*)d_out;

    float* hptr = nullptr;
    cudaGetSymbolAddress((void**)&hptr, g_h);
    int* degptr = nullptr;
    cudaGetSymbolAddress((void**)&degptr, g_deg);

    static cudaStream_t s2 = nullptr;
    static cudaEvent_t ev_fork = nullptr, ev_csr = nullptr,
                       ev_e1[3], ev_e2[3],
                       ev_g2 = nullptr, ev_g3 = nullptr;
    if (!s2){
        cudaStreamCreateWithFlags(&s2, cudaStreamNonBlocking);
        cudaEventCreateWithFlags(&ev_fork, cudaEventDisableTiming);
        cudaEventCreateWithFlags(&ev_csr,  cudaEventDisableTiming);
        cudaEventCreateWithFlags(&ev_g2,   cudaEventDisableTiming);
        cudaEventCreateWithFlags(&ev_g3,   cudaEventDisableTiming);
        for (int c = 0; c < 3; c++){
            cudaEventCreateWithFlags(&ev_e1[c], cudaEventDisableTiming);
            cudaEventCreateWithFlags(&ev_e2[c], cudaEventDisableTiming);
        }
        cudaFuncSetAttribute(gemmT, cudaFuncAttributeMaxDynamicSharedMemorySize,
                             SMEM_T);
    }

    int eb4 = (NE/4 + 255)/256;
    int gg_full = (NN + 63)/64;
    int ne3 = (NN + 31)/32;

    const int cst[3]  = {0, C0, C0 + C1};
    const int crw[3]  = {C0, C1, C2};

    // ---- CSR build on side stream, overlapped with layer-1 GEMM ----
    cudaEventRecord(ev_fork, 0);
    cudaStreamWaitEvent(s2, ev_fork, 0);
    cudaMemsetAsync(degptr, 0, NN*sizeof(int), s2);
    hist_k<<<eb4,256,0,s2>>>(ei);
    scan_k<<<1,1024,0,s2>>>();
    scatter_k<<<eb4,256,0,s2>>>(ei);
    cudaEventRecord(ev_csr, s2);

    gemmT<<<gg_full,256,SMEM_T>>>(x, p[0],p[1],p[2],p[3],p[4],p[5],p[6],p[7],
                                  0, 0, 0);
    cudaStreamWaitEvent(0, ev_csr, 0);

    // ---- layer-1 edges (3 chunks) cascading layer-2 GEMM chunks on s2 ----
    for (int c = 0; c < 3; c++){
        edge64<<<(crw[c]+7)/8,256>>>(0, cst[c], crw[c]);
        cudaEventRecord(ev_e1[c], 0);
        cudaStreamWaitEvent(s2, ev_e1[c], 0);
        gemmT<<<(crw[c]+63)/64,256,SMEM_T,s2>>>(hptr,
            p[8],p[9],p[10],p[11],p[12],p[13],p[14],p[15], cst[c], 1, 1);
    }
    cudaEventRecord(ev_g2, s2);
    cudaStreamWaitEvent(0, ev_g2, 0);

    // ---- layer-2 edges (3 chunks) cascading gemm3 chunks on s2 ----
    for (int c = 0; c < 3; c++){
        edge64<<<(crw[c]+7)/8,256>>>(1, cst[c], crw[c]);
        cudaEventRecord(ev_e2[c], 0);
        cudaStreamWaitEvent(s2, ev_e2[c], 0);
        gemm3<<<(crw[c]+255)/256,256,0,s2>>>(hptr,
            p[16],p[17],p[18],p[19],p[20],p[21],p[22],p[23], noise,
            cst[c], crw[c]);
    }
    cudaEventRecord(ev_g3, s2);
    cudaStreamWaitEvent(0, ev_g3, 0);

    edge3<<<ne3,256>>>(out);
}

// round 16
// speedup vs baseline: 1.0473x; 1.0473x over previous
#include <cuda_runtime.h>
#include <cuda_fp16.h>
#include <mma.h>
#include <math.h>

using namespace nvcuda;

#define NN 100000
#define NE 3200000
#define CH0 70016              // chunk-0 rows (~70%; multiple of 64 and of 16)

#define PAD 72                 // half stride for wmma smem tiles
#define OPAD 68                // float stride for epilogue buffers
#define SM_HALVES (7*64*PAD)
#define SMEM_T (SM_HALVES*2)   // 64512 bytes

// ---------------- scratch (device globals) ----------------
__device__ __align__(16) uint2 g_qh[2*NN*16];    // q fp16: per node,lane {q0..3}
__device__ __align__(16) uint4 g_kvh[2*NN*16];   // per node,lane: {k0..3,v0..3} fp16
__device__ __align__(16) float g_s [2*NN*64];
__device__ __align__(16) float g_h [NN*64];
__device__ __align__(16) float g_q3 [NN*4];
__device__ __align__(16) float g_s3 [NN*4];
__device__ __align__(32) float g_kv3[NN*8];
__device__ int g_deg[NN];
__device__ int g_ptr[NN+1];
__device__ int g_rank[NE];
__device__ int g_esrc[NE];

// ---------------- CSR build ----------------
__global__ void hist_k(const int* __restrict__ ei){
    int i = blockIdx.x*blockDim.x + threadIdx.x;
    if (i < NE/4){
        int4 d = ((const int4*)(ei + NE))[i];
        int4 r;
        r.x = atomicAdd(&g_deg[d.x], 1);
        r.y = atomicAdd(&g_deg[d.y], 1);
        r.z = atomicAdd(&g_deg[d.z], 1);
        r.w = atomicAdd(&g_deg[d.w], 1);
        ((int4*)g_rank)[i] = r;
    }
}
__global__ void __launch_bounds__(1024) scan_k(){
    __shared__ int sh[1024];
    int t = threadIdx.x;
    int carry = 0;
    for (int base = 0; base < NN; base += 4096){
        int v[4]; int s = 0;
        #pragma unroll
        for (int j = 0; j < 4; j++){
            int idx = base + t*4 + j;
            v[j] = (idx < NN) ? g_deg[idx] : 0;
            s += v[j];
        }
        sh[t] = s; __syncthreads();
        #pragma unroll
        for (int off = 1; off < 1024; off <<= 1){
            int x = (t >= off) ? sh[t-off] : 0;
            __syncthreads();
            sh[t] += x;
            __syncthreads();
        }
        int total = sh[1023];
        int excl = carry + sh[t] - s;
        #pragma unroll
        for (int j = 0; j < 4; j++){
            int idx = base + t*4 + j;
            if (idx < NN) g_ptr[idx] = excl;
            excl += v[j];
        }
        carry += total;
        __syncthreads();
    }
    if (t == 0) g_ptr[NN] = carry;
}
__global__ void scatter_k(const int* __restrict__ ei){
    int i = blockIdx.x*blockDim.x + threadIdx.x;
    if (i < NE/4){
        int4 s = ((const int4*)ei)[i];
        int4 d = ((const int4*)(ei + NE))[i];
        int4 r = ((const int4*)g_rank)[i];
        g_esrc[g_ptr[d.x] + r.x] = s.x;
        g_esrc[g_ptr[d.y] + r.y] = s.y;
        g_esrc[g_ptr[d.z] + r.z] = s.z;
        g_esrc[g_ptr[d.w] + r.w] = s.w;
    }
}

// ---------------- tensor-core quad GEMM, vectorized staging -----------------
__global__ void __launch_bounds__(256) gemmT(
    const float* __restrict__ X,
    const float* __restrict__ Wq, const float* __restrict__ bq,
    const float* __restrict__ Wk, const float* __restrict__ bk,
    const float* __restrict__ Wv, const float* __restrict__ bv,
    const float* __restrict__ Ws, const float* __restrict__ bs,
    int row0, int buf, int addres)
{
    extern __shared__ __half sm[];
    __half* Ah  = sm;
    __half* Al  = sm + 64*PAD;
    __half* Bq  = sm + 2*64*PAD;
    __half* Bk  = sm + 3*64*PAD;
    __half* Bv  = sm + 4*64*PAD;
    __half* Bsh = sm + 5*64*PAD;
    __half* Bsl = sm + 6*64*PAD;

    int t   = threadIdx.x;
    int r0  = row0 + blockIdx.x*64;
    int wid = t >> 5;
    int grp = wid >> 2;
    int rt  = wid & 3;

    uint2* QH = g_qh + (size_t)buf*NN*16;
    float* S  = g_s  + (size_t)buf*NN*64;
    uint4* KV = g_kvh + (size_t)buf*NN*16;

    // ---- stage X (split hi/lo), STS.64 ----
    #pragma unroll
    for (int i = 0; i < 4; i++){
        int s = t + i*256;
        int row = s >> 4, c0 = (s & 15)*4;
        float4 xv = make_float4(0.f,0.f,0.f,0.f);
        if (r0 + row < NN) xv = ((const float4*)X)[(size_t)(r0+row)*16 + (c0>>2)];
        __half2 h0 = __floats2half2_rn(xv.x, xv.y);
        __half2 h1 = __floats2half2_rn(xv.z, xv.w);
        float2 f0 = __half22float2(h0), f1 = __half22float2(h1);
        __half2 l0 = __floats2half2_rn(xv.x - f0.x, xv.y - f0.y);
        __half2 l1 = __floats2half2_rn(xv.z - f1.x, xv.w - f1.y);
        uint2 uh, ul;
        *(__half2*)&uh.x = h0; *(__half2*)&uh.y = h1;
        *(__half2*)&ul.x = l0; *(__half2*)&ul.y = l1;
        *(uint2*)&Ah[row*PAD + c0] = uh;
        *(uint2*)&Al[row*PAD + c0] = ul;
    }
    // ---- stage weights, STS.128 ----
    #pragma unroll
    for (int i = 0; i < 2; i++){
        int ch = t + i*256;
        int k = ch >> 3, c0 = (ch & 7)*8;
        int q4 = k*16 + (c0>>2);
        float4 a, b; uint4 u;
        a = ((const float4*)Wq)[q4]; b = ((const float4*)Wq)[q4+1];
        *(__half2*)&u.x = __floats2half2_rn(a.x,a.y);
        *(__half2*)&u.y = __floats2half2_rn(a.z,a.w);
        *(__half2*)&u.z = __floats2half2_rn(b.x,b.y);
        *(__half2*)&u.w = __floats2half2_rn(b.z,b.w);
        *(uint4*)&Bq[k*PAD + c0] = u;
        a = ((const float4*)Wk)[q4]; b = ((const float4*)Wk)[q4+1];
        *(__half2*)&u.x = __floats2half2_rn(a.x,a.y);
        *(__half2*)&u.y = __floats2half2_rn(a.z,a.w);
        *(__half2*)&u.z = __floats2half2_rn(b.x,b.y);
        *(__half2*)&u.w = __floats2half2_rn(b.z,b.w);
        *(uint4*)&Bk[k*PAD + c0] = u;
        a = ((const float4*)Wv)[q4]; b = ((const float4*)Wv)[q4+1];
        *(__half2*)&u.x = __floats2half2_rn(a.x,a.y);
        *(__half2*)&u.y = __floats2half2_rn(a.z,a.w);
        *(__half2*)&u.z = __floats2half2_rn(b.x,b.y);
        *(__half2*)&u.w = __floats2half2_rn(b.z,b.w);
        *(uint4*)&Bv[k*PAD + c0] = u;
        a = ((const float4*)Ws)[q4]; b = ((const float4*)Ws)[q4+1];
        __half2 h0 = __floats2half2_rn(a.x,a.y);
        __half2 h1 = __floats2half2_rn(a.z,a.w);
        __half2 h2 = __floats2half2_rn(b.x,b.y);
        __half2 h3 = __floats2half2_rn(b.z,b.w);
        *(__half2*)&u.x = h0; *(__half2*)&u.y = h1;
        *(__half2*)&u.z = h2; *(__half2*)&u.w = h3;
        *(uint4*)&Bsh[k*PAD + c0] = u;
        float2 g0 = __half22float2(h0), g1 = __half22float2(h1);
        float2 g2 = __half22float2(h2), g3 = __half22float2(h3);
        *(__half2*)&u.x = __floats2half2_rn(a.x-g0.x, a.y-g0.y);
        *(__half2*)&u.y = __floats2half2_rn(a.z-g1.x, a.w-g1.y);
        *(__half2*)&u.z = __floats2half2_rn(b.x-g2.x, b.y-g2.y);
        *(__half2*)&u.w = __floats2half2_rn(b.z-g3.x, b.w-g3.y);
        *(uint4*)&Bsl[k*PAD + c0] = u;
    }
    __syncthreads();

    wmma::fragment<wmma::accumulator, 16,16,16, float> acc[8];
    #pragma unroll
    for (int i = 0; i < 8; i++) wmma::fill_fragment(acc[i], 0.f);

    #pragma unroll
    for (int kk = 0; kk < 4; kk++){
        int ka = kk*16;
        wmma::fragment<wmma::matrix_a, 16,16,16, __half, wmma::row_major> ah, al;
        wmma::load_matrix_sync(ah, Ah + rt*16*PAD + ka, PAD);
        wmma::load_matrix_sync(al, Al + rt*16*PAD + ka, PAD);
        wmma::fragment<wmma::matrix_b, 16,16,16, __half, wmma::row_major> b;
        if (grp == 0){
            #pragma unroll
            for (int ct = 0; ct < 4; ct++){
                wmma::load_matrix_sync(b, Bq + ka*PAD + ct*16, PAD);
                wmma::mma_sync(acc[ct], ah, b, acc[ct]);
                wmma::mma_sync(acc[ct], al, b, acc[ct]);
            }
            #pragma unroll
            for (int ct = 0; ct < 4; ct++){
                wmma::load_matrix_sync(b, Bk + ka*PAD + ct*16, PAD);
                wmma::mma_sync(acc[4+ct], ah, b, acc[4+ct]);
                wmma::mma_sync(acc[4+ct], al, b, acc[4+ct]);
            }
        } else {
            #pragma unroll
            for (int ct = 0; ct < 4; ct++){
                wmma::load_matrix_sync(b, Bv + ka*PAD + ct*16, PAD);
                wmma::mma_sync(acc[ct], ah, b, acc[ct]);
            }
            #pragma unroll
            for (int ct = 0; ct < 4; ct++){
                wmma::load_matrix_sync(b, Bsh + ka*PAD + ct*16, PAD);
                wmma::mma_sync(acc[4+ct], ah, b, acc[4+ct]);
                wmma::mma_sync(acc[4+ct], al, b, acc[4+ct]);
                wmma::load_matrix_sync(b, Bsl + ka*PAD + ct*16, PAD);
                wmma::mma_sync(acc[4+ct], ah, b, acc[4+ct]);
            }
        }
    }
    __syncthreads();

    float* obuf0 = (float*)sm;
    float* obuf1 = (float*)sm + 64*OPAD;
    bool res = (addres != 0);

    // ---- round A: Q (fp16) + V ----
    {
        float* dst = (grp == 0) ? obuf0 : obuf1;
        #pragma unroll
        for (int ct = 0; ct < 4; ct++)
            wmma::store_matrix_sync(dst + rt*16*OPAD + ct*16, acc[ct], OPAD,
                                    wmma::mem_row_major);
    }
    __syncthreads();
    #pragma unroll
    for (int i = 0; i < 4; i++){
        int e = t + i*256;
        int row = e >> 4, c4 = e & 15;
        if (r0 + row < NN){
            size_t grow = (size_t)(r0+row);
            const float* sq = obuf0 + row*OPAD + c4*4;
            float4 bqv = ((const float4*)bq)[c4];
            __half2 q0 = __floats2half2_rn(sq[0]+bqv.x, sq[1]+bqv.y);
            __half2 q1 = __floats2half2_rn(sq[2]+bqv.z, sq[3]+bqv.w);
            uint2 uq; *(__half2*)&uq.x = q0; *(__half2*)&uq.y = q1;
            QH[grow*16 + c4] = uq;
            const float* sv = obuf1 + row*OPAD + c4*4;
            float4 bvv = ((const float4*)bv)[c4];
            __half2 h0 = __floats2half2_rn(sv[0]+bvv.x, sv[1]+bvv.y);
            __half2 h1 = __floats2half2_rn(sv[2]+bvv.z, sv[3]+bvv.w);
            uint2 u; *(__half2*)&u.x = h0; *(__half2*)&u.y = h1;
            ((uint2*)&KV[grow*16 + c4])[1] = u;
        }
    }
    __syncthreads();

    // ---- round B: K + S ----
    {
        float* dst = (grp == 0) ? obuf0 : obuf1;
        #pragma unroll
        for (int ct = 0; ct < 4; ct++)
            wmma::store_matrix_sync(dst + rt*16*OPAD + ct*16, acc[4+ct], OPAD,
                                    wmma::mem_row_major);
    }
    __syncthreads();
    #pragma unroll
    for (int i = 0; i < 4; i++){
        int e = t + i*256;
        int row = e >> 4, c4 = e & 15;
        if (r0 + row < NN){
            size_t grow = (size_t)(r0+row);
            const float* sk_ = obuf0 + row*OPAD + c4*4;
            float4 bkv = ((const float4*)bk)[c4];
            __half2 h0 = __floats2half2_rn(sk_[0]+bkv.x, sk_[1]+bkv.y);
            __half2 h1 = __floats2half2_rn(sk_[2]+bkv.z, sk_[3]+bkv.w);
            uint2 u; *(__half2*)&u.x = h0; *(__half2*)&u.y = h1;
            ((uint2*)&KV[grow*16 + c4])[0] = u;
            const float* ss = obuf1 + row*OPAD + c4*4;
            float4 bsv = ((const float4*)bs)[c4];
            float4 os = make_float4(ss[0]+bsv.x, ss[1]+bsv.y,
                                    ss[2]+bsv.z, ss[3]+bsv.w);
            if (res){
                float4 xv = ((const float4*)X)[grow*16 + c4];
                os.x += xv.x; os.y += xv.y; os.z += xv.z; os.w += xv.w;
            }
            ((float4*)S)[grow*16 + c4] = os;
        }
    }
}

// ------- fused per-node attention, D=64: one node/warp, fp16 q, HFMA2 dots --
__device__ __forceinline__ float dot4hh(__half2 q01, __half2 q23,
                                        unsigned a, unsigned b){
    __half2 p = __hmul2(q01, *(__half2*)&a);
    p = __hfma2(q23, *(__half2*)&b, p);
    float2 f = __half22float2(p);
    return f.x + f.y;
}
__device__ __forceinline__ void accv(float4& acc, float e, unsigned a, unsigned b){
    float2 f01 = __half22float2(*(__half2*)&a);
    float2 f23 = __half22float2(*(__half2*)&b);
    acc.x += e*f01.x; acc.y += e*f01.y; acc.z += e*f23.x; acc.w += e*f23.y;
}

__global__ void __launch_bounds__(256) edge64(int buf, int base, int nnodes){
    int lid = blockIdx.x*8 + (threadIdx.x >> 5);
    if (lid >= nnodes) return;
    int gid = base + lid;
    int lane = threadIdx.x & 15;
    int half = (threadIdx.x >> 4) & 1;
    unsigned gmask = 0xffffu << (threadIdx.x & 16);

    const uint2* QH = g_qh + (size_t)buf*NN*16;
    const float* S  = g_s  + (size_t)buf*NN*64;
    const uint4* KV = g_kvh + (size_t)buf*NN*16;

    uint2 qr = QH[(size_t)gid*16 + lane];
    __half2 q01 = *(__half2*)&qr.x;
    __half2 q23 = *(__half2*)&qr.y;
    int beg = g_ptr[gid], end = g_ptr[gid+1];

    float4 acc = make_float4(0.f,0.f,0.f,0.f);
    float ssum = 0.f;

    for (int i = beg + half*4; i + 4 <= end; i += 8){
        int s0 = g_esrc[i],   s1 = g_esrc[i+1];
        int s2 = g_esrc[i+2], s3 = g_esrc[i+3];
        uint4 kv0 = KV[(size_t)s0*16 + lane];
        uint4 kv1 = KV[(size_t)s1*16 + lane];
        uint4 kv2 = KV[(size_t)s2*16 + lane];
        uint4 kv3 = KV[(size_t)s3*16 + lane];
        float d0 = dot4hh(q01, q23, kv0.x, kv0.y);
        float d1 = dot4hh(q01, q23, kv1.x, kv1.y);
        float d2 = dot4hh(q01, q23, kv2.x, kv2.y);
        float d3 = dot4hh(q01, q23, kv3.x, kv3.y);
        #pragma unroll
        for (int o = 8; o >= 1; o >>= 1){
            d0 += __shfl_xor_sync(gmask, d0, o);
            d1 += __shfl_xor_sync(gmask, d1, o);
            d2 += __shfl_xor_sync(gmask, d2, o);
            d3 += __shfl_xor_sync(gmask, d3, o);
        }
        float e0 = __expf(d0*0.125f);
        float e1 = __expf(d1*0.125f);
        float e2 = __expf(d2*0.125f);
        float e3 = __expf(d3*0.125f);
        ssum += (e0 + e1) + (e2 + e3);
        accv(acc, e0, kv0.z, kv0.w); accv(acc, e1, kv1.z, kv1.w);
        accv(acc, e2, kv2.z, kv2.w); accv(acc, e3, kv3.z, kv3.w);
    }
    if (half == 0){
        for (int i = beg + ((end - beg) & ~3); i < end; i++){
            int s0 = g_esrc[i];
            uint4 kv0 = KV[(size_t)s0*16 + lane];
            float d0 = dot4hh(q01, q23, kv0.x, kv0.y);
            #pragma unroll
            for (int o = 8; o >= 1; o >>= 1)
                d0 += __shfl_xor_sync(gmask, d0, o);
            float e0 = __expf(d0*0.125f);
            ssum += e0;
            accv(acc, e0, kv0.z, kv0.w);
        }
    }
    ssum  += __shfl_xor_sync(0xffffffffu, ssum,  16);
    acc.x += __shfl_xor_sync(0xffffffffu, acc.x, 16);
    acc.y += __shfl_xor_sync(0xffffffffu, acc.y, 16);
    acc.z += __shfl_xor_sync(0xffffffffu, acc.z, 16);
    acc.w += __shfl_xor_sync(0xffffffffu, acc.w, 16);

    float inv = 1.0f / (ssum + 1e-16f);
    float4 sk = ((const float4*)S)[(size_t)gid*16 + lane];
    float4 o;
    o.x = tanhf(acc.x*inv + sk.x);
    o.y = tanhf(acc.y*inv + sk.y);
    o.z = tanhf(acc.z*inv + sk.z);
    o.w = tanhf(acc.w*inv + sk.w);
    if (half == 0)
        ((float4*)g_h)[(size_t)gid*16 + lane] = o;
}

// ---------------- layer 3: 64 -> (3 x 4) GEMM over row range ----------------
__global__ void __launch_bounds__(256) gemm3(
    const float* __restrict__ X,
    const float* __restrict__ Wq, const float* __restrict__ bq,
    const float* __restrict__ Wk, const float* __restrict__ bk,
    const float* __restrict__ Wv, const float* __restrict__ bv,
    const float* __restrict__ Ws, const float* __restrict__ bs,
    const float* __restrict__ noise, int row0)
{
    __shared__ float w[64*12];
    __shared__ float bias[12];
    int t = threadIdx.x;
    if (t < 192){
        int kk = t/3, j = t%3;
        w[kk*12 + 0 + j] = Wq[t];
        w[kk*12 + 3 + j] = Wk[t];
        w[kk*12 + 6 + j] = Wv[t];
        w[kk*12 + 9 + j] = Ws[t];
    }
    if (t < 3){
        bias[t]   = bq[t];
        bias[3+t] = bk[t];
        bias[6+t] = bv[t];
        bias[9+t] = bs[t];
    }
    __syncthreads();
    int node = row0 + blockIdx.x*256 + t;
    if (node >= NN) return;
    float acc[12];
    #pragma unroll
    for (int j = 0; j < 12; j++) acc[j] = 0.f;
    #pragma unroll
    for (int kk = 0; kk < 16; kk++){
        float4 xv = ((const float4*)X)[(size_t)node*16 + kk];
        #pragma unroll
        for (int j = 0; j < 12; j++){
            acc[j] += xv.x * w[(kk*4+0)*12+j]
                    + xv.y * w[(kk*4+1)*12+j]
                    + xv.z * w[(kk*4+2)*12+j]
                    + xv.w * w[(kk*4+3)*12+j];
        }
    }
    float4 q3 = make_float4(acc[0]+bias[0], acc[1]+bias[1], acc[2]+bias[2], 0.f);
    float4 kva = make_float4(acc[3]+bias[3], acc[4]+bias[4], acc[5]+bias[5],
                             acc[6]+bias[6]);
    float4 kvb = make_float4(acc[7]+bias[7], acc[8]+bias[8], 0.f, 0.f);
    float4 s3 = make_float4(acc[9]+bias[9]   + 0.1f*noise[node*3+0],
                            acc[10]+bias[10] + 0.1f*noise[node*3+1],
                            acc[11]+bias[11] + 0.1f*noise[node*3+2], 0.f);
    ((float4*)g_q3)[node] = q3;
    ((float4*)g_kv3)[node*2]   = kva;
    ((float4*)g_kv3)[node*2+1] = kvb;
    ((float4*)g_s3)[node] = s3;
}

// ------- layer-3 per-node attention: 8 lanes per node -------
__global__ void __launch_bounds__(256) edge3(float* __restrict__ out){
    int nid = blockIdx.x*32 + (threadIdx.x >> 3);
    if (nid >= NN) return;
    int lane = threadIdx.x & 7;
    unsigned gmask = 0xFFu << (threadIdx.x & 24);

    float4 q = ((const float4*)g_q3)[nid];
    int beg = g_ptr[nid], end = g_ptr[nid+1];
    float sum = 0.f, ax = 0.f, ay = 0.f, az = 0.f;
    for (int i = beg + lane; i < end; i += 8){
        int s0 = g_esrc[i];
        float4 a0 = ((const float4*)g_kv3)[s0*2];
        float4 b0 = ((const float4*)g_kv3)[s0*2+1];
        float e0 = __expf((q.x*a0.x + q.y*a0.y + q.z*a0.z)*0.57735026919f);
        sum += e0;
        ax += e0*a0.w; ay += e0*b0.x; az += e0*b0.y;
    }
    #pragma unroll
    for (int o = 4; o >= 1; o >>= 1){
        sum += __shfl_xor_sync(gmask, sum, o);
        ax  += __shfl_xor_sync(gmask, ax,  o);
        ay  += __shfl_xor_sync(gmask, ay,  o);
        az  += __shfl_xor_sync(gmask, az,  o);
    }
    if (lane == 0){
        float inv = 1.0f / (sum + 1e-16f);
        float4 s3 = ((const float4*)g_s3)[nid];
        out[nid*3+0] = ax*inv + s3.x;
        out[nid*3+1] = ay*inv + s3.y;
        out[nid*3+2] = az*inv + s3.z;
    }
}

// ---------------- launcher (round-14 measured-optimal schedule) ----------------
extern "C" void kernel_launch(void* const* d_in, const int* in_sizes, int n_in,
                              void* d_out, int out_size)
{
    const float* x     = (const float*)d_in[0];
    const int*   ei    = (const int*)d_in[1];
    const float* noise = (const float*)d_in[2];
    const float* p[24];
    for (int i = 0; i < 24; i++) p[i] = (const float*)d_in[3+i];
    float* out = (float*)d_out;

    float* hptr = nullptr;
    cudaGetSymbolAddress((void**)&hptr, g_h);
    int* degptr = nullptr;
    cudaGetSymbolAddress((void**)&degptr, g_deg);

    static cudaStream_t s2 = nullptr;
    static cudaEvent_t ev_fork = nullptr, ev_csr = nullptr,
                       ev_e1a = nullptr, ev_g2a = nullptr,
                       ev_e2a = nullptr, ev_g3a = nullptr;
    if (!s2){
        cudaStreamCreateWithFlags(&s2, cudaStreamNonBlocking);
        cudaEventCreateWithFlags(&ev_fork, cudaEventDisableTiming);
        cudaEventCreateWithFlags(&ev_csr,  cudaEventDisableTiming);
        cudaEventCreateWithFlags(&ev_e1a,  cudaEventDisableTiming);
        cudaEventCreateWithFlags(&ev_g2a,  cudaEventDisableTiming);
        cudaEventCreateWithFlags(&ev_e2a,  cudaEventDisableTiming);
        cudaEventCreateWithFlags(&ev_g3a,  cudaEventDisableTiming);
        cudaFuncSetAttribute(gemmT, cudaFuncAttributeMaxDynamicSharedMemorySize,
                             SMEM_T);
    }

    int eb4 = (NE/4 + 255)/256;
    const int CH1 = NN - CH0;
    int gg_full = (NN + 63)/64;
    int gg_a = CH0/64;
    int gg_b = (CH1 + 63)/64;
    int ng_a = (CH0 + 7)/8, ng_b = (CH1 + 7)/8;
    int nb3_a = (CH0 + 255)/256, nb3_b = (CH1 + 255)/256;
    int ne3 = (NN + 31)/32;

    // ---- CSR build on side stream, overlapped with layer-1 GEMM ----
    cudaEventRecord(ev_fork, 0);
    cudaStreamWaitEvent(s2, ev_fork, 0);
    cudaMemsetAsync(degptr, 0, NN*sizeof(int), s2);
    hist_k<<<eb4,256,0,s2>>>(ei);
    scan_k<<<1,1024,0,s2>>>();
    scatter_k<<<eb4,256,0,s2>>>(ei);
    cudaEventRecord(ev_csr, s2);

    gemmT<<<gg_full,256,SMEM_T>>>(x, p[0],p[1],p[2],p[3],p[4],p[5],p[6],p[7],
                                  0, 0, 0);

    cudaStreamWaitEvent(0, ev_csr, 0);
    edge64<<<ng_a,256>>>(0, 0, CH0);
    cudaEventRecord(ev_e1a, 0);
    edge64<<<ng_b,256>>>(0, CH0, CH1);

    cudaStreamWaitEvent(s2, ev_e1a, 0);
    gemmT<<<gg_a,256,SMEM_T,s2>>>(hptr, p[8],p[9],p[10],p[11],p[12],p[13],p[14],p[15],
                                  0, 1, 1);
    cudaEventRecord(ev_g2a, s2);

    gemmT<<<gg_b,256,SMEM_T>>>(hptr, p[8],p[9],p[10],p[11],p[12],p[13],p[14],p[15],
                               CH0, 1, 1);
    cudaStreamWaitEvent(0, ev_g2a, 0);

    edge64<<<ng_a,256>>>(1, 0, CH0);
    cudaEventRecord(ev_e2a, 0);
    edge64<<<ng_b,256>>>(1, CH0, CH1);

    cudaStreamWaitEvent(s2, ev_e2a, 0);
    gemm3<<<nb3_a,256,0,s2>>>(hptr, p[16],p[17],p[18],p[19],p[20],p[21],p[22],p[23],
                              noise, 0);
    cudaEventRecord(ev_g3a, s2);

    gemm3<<<nb3_b,256>>>(hptr, p[16],p[17],p[18],p[19],p[20],p[21],p[22],p[23],
                         noise, CH0);
    cudaStreamWaitEvent(0, ev_g3a, 0);
    edge3<<<ne3,256>>>(out);
}

// round 17
// speedup vs baseline: 1.0716x; 1.0233x over previous
#include <cuda_runtime.h>
#include <cuda_fp16.h>
#include <mma.h>
#include <math.h>

using namespace nvcuda;

#define NN 100000
#define NE 3200000
#define CH0 70016              // chunk-0 rows (~70%; multiple of 64 and of 16)

#define PAD 72                 // half stride for wmma smem tiles
#define OPAD 68                // float stride for epilogue buffers
#define SM_HALVES (7*64*PAD)
#define SMEM_T (SM_HALVES*2)   // 64512 bytes

// ---------------- scratch (device globals) ----------------
__device__ __align__(16) uint2 g_qh[2*NN*16];    // q fp16: per node,lane {q0..3}
__device__ __align__(16) uint4 g_kvh[2*NN*16];   // per node,lane: {k0..3,v0..3} fp16
__device__ __align__(16) float g_s [2*NN*64];
__device__ __align__(16) float g_h [NN*64];
__device__ __align__(16) float g_q3 [NN*4];
__device__ __align__(16) float g_s3 [NN*4];
__device__ __align__(32) float g_kv3[NN*8];
__device__ int g_deg[NN];
__device__ int g_ptr[NN+1];
__device__ int g_rank[NE];
__device__ int g_esrc[NE];

// ---------------- CSR build ----------------
__global__ void hist_k(const int* __restrict__ ei){
    int i = blockIdx.x*blockDim.x + threadIdx.x;
    if (i < NE/4){
        int4 d = ((const int4*)(ei + NE))[i];
        int4 r;
        r.x = atomicAdd(&g_deg[d.x], 1);
        r.y = atomicAdd(&g_deg[d.y], 1);
        r.z = atomicAdd(&g_deg[d.z], 1);
        r.w = atomicAdd(&g_deg[d.w], 1);
        ((int4*)g_rank)[i] = r;
    }
}
// warp-shuffle scan: 3 barriers per 4096-tile (was 20)
__global__ void __launch_bounds__(1024) scan_k(){
    __shared__ int wsum[32];
    int t = threadIdx.x, lane = t & 31, w = t >> 5;
    int carry = 0;
    for (int base = 0; base < NN; base += 4096){
        int v[4]; int s = 0;
        #pragma unroll
        for (int j = 0; j < 4; j++){
            int idx = base + t*4 + j;
            v[j] = (idx < NN) ? g_deg[idx] : 0;
            s += v[j];
        }
        // inclusive warp scan of per-thread sums
        int inc = s;
        #pragma unroll
        for (int off = 1; off < 32; off <<= 1){
            int x = __shfl_up_sync(0xffffffffu, inc, off);
            if (lane >= off) inc += x;
        }
        if (lane == 31) wsum[w] = inc;
        __syncthreads();
        if (w == 0){
            int x = wsum[lane];
            #pragma unroll
            for (int off = 1; off < 32; off <<= 1){
                int y = __shfl_up_sync(0xffffffffu, x, off);
                if (lane >= off) x += y;
            }
            wsum[lane] = x;            // inclusive warp prefix
        }
        __syncthreads();
        int woff  = (w > 0) ? wsum[w-1] : 0;
        int total = wsum[31];
        int excl  = carry + woff + (inc - s);
        #pragma unroll
        for (int j = 0; j < 4; j++){
            int idx = base + t*4 + j;
            if (idx < NN) g_ptr[idx] = excl;
            excl += v[j];
        }
        carry += total;
        __syncthreads();               // protect wsum for next tile
    }
    if (t == 0) g_ptr[NN] = carry;
}
// destination-split scatter (rank trick -> order-independent, no atomics)
__global__ void scatter_k(const int* __restrict__ ei, int dlo, int dhi){
    int i = blockIdx.x*blockDim.x + threadIdx.x;
    if (i < NE/4){
        int4 s = ((const int4*)ei)[i];
        int4 d = ((const int4*)(ei + NE))[i];
        int4 r = ((const int4*)g_rank)[i];
        if (d.x >= dlo && d.x < dhi) g_esrc[g_ptr[d.x] + r.x] = s.x;
        if (d.y >= dlo && d.y < dhi) g_esrc[g_ptr[d.y] + r.y] = s.y;
        if (d.z >= dlo && d.z < dhi) g_esrc[g_ptr[d.z] + r.z] = s.z;
        if (d.w >= dlo && d.w < dhi) g_esrc[g_ptr[d.w] + r.w] = s.w;
    }
}

// ---------------- tensor-core quad GEMM, vectorized staging -----------------
__global__ void __launch_bounds__(256) gemmT(
    const float* __restrict__ X,
    const float* __restrict__ Wq, const float* __restrict__ bq,
    const float* __restrict__ Wk, const float* __restrict__ bk,
    const float* __restrict__ Wv, const float* __restrict__ bv,
    const float* __restrict__ Ws, const float* __restrict__ bs,
    int row0, int buf, int addres)
{
    extern __shared__ __half sm[];
    __half* Ah  = sm;
    __half* Al  = sm + 64*PAD;
    __half* Bq  = sm + 2*64*PAD;
    __half* Bk  = sm + 3*64*PAD;
    __half* Bv  = sm + 4*64*PAD;
    __half* Bsh = sm + 5*64*PAD;
    __half* Bsl = sm + 6*64*PAD;

    int t   = threadIdx.x;
    int r0  = row0 + blockIdx.x*64;
    int wid = t >> 5;
    int grp = wid >> 2;
    int rt  = wid & 3;

    uint2* QH = g_qh + (size_t)buf*NN*16;
    float* S  = g_s  + (size_t)buf*NN*64;
    uint4* KV = g_kvh + (size_t)buf*NN*16;

    // ---- stage X (split hi/lo), STS.64 ----
    #pragma unroll
    for (int i = 0; i < 4; i++){
        int s = t + i*256;
        int row = s >> 4, c0 = (s & 15)*4;
        float4 xv = make_float4(0.f,0.f,0.f,0.f);
        if (r0 + row < NN) xv = ((const float4*)X)[(size_t)(r0+row)*16 + (c0>>2)];
        __half2 h0 = __floats2half2_rn(xv.x, xv.y);
        __half2 h1 = __floats2half2_rn(xv.z, xv.w);
        float2 f0 = __half22float2(h0), f1 = __half22float2(h1);
        __half2 l0 = __floats2half2_rn(xv.x - f0.x, xv.y - f0.y);
        __half2 l1 = __floats2half2_rn(xv.z - f1.x, xv.w - f1.y);
        uint2 uh, ul;
        *(__half2*)&uh.x = h0; *(__half2*)&uh.y = h1;
        *(__half2*)&ul.x = l0; *(__half2*)&ul.y = l1;
        *(uint2*)&Ah[row*PAD + c0] = uh;
        *(uint2*)&Al[row*PAD + c0] = ul;
    }
    // ---- stage weights, STS.128 ----
    #pragma unroll
    for (int i = 0; i < 2; i++){
        int ch = t + i*256;
        int k = ch >> 3, c0 = (ch & 7)*8;
        int q4 = k*16 + (c0>>2);
        float4 a, b; uint4 u;
        a = ((const float4*)Wq)[q4]; b = ((const float4*)Wq)[q4+1];
        *(__half2*)&u.x = __floats2half2_rn(a.x,a.y);
        *(__half2*)&u.y = __floats2half2_rn(a.z,a.w);
        *(__half2*)&u.z = __floats2half2_rn(b.x,b.y);
        *(__half2*)&u.w = __floats2half2_rn(b.z,b.w);
        *(uint4*)&Bq[k*PAD + c0] = u;
        a = ((const float4*)Wk)[q4]; b = ((const float4*)Wk)[q4+1];
        *(__half2*)&u.x = __floats2half2_rn(a.x,a.y);
        *(__half2*)&u.y = __floats2half2_rn(a.z,a.w);
        *(__half2*)&u.z = __floats2half2_rn(b.x,b.y);
        *(__half2*)&u.w = __floats2half2_rn(b.z,b.w);
        *(uint4*)&Bk[k*PAD + c0] = u;
        a = ((const float4*)Wv)[q4]; b = ((const float4*)Wv)[q4+1];
        *(__half2*)&u.x = __floats2half2_rn(a.x,a.y);
        *(__half2*)&u.y = __floats2half2_rn(a.z,a.w);
        *(__half2*)&u.z = __floats2half2_rn(b.x,b.y);
        *(__half2*)&u.w = __floats2half2_rn(b.z,b.w);
        *(uint4*)&Bv[k*PAD + c0] = u;
        a = ((const float4*)Ws)[q4]; b = ((const float4*)Ws)[q4+1];
        __half2 h0 = __floats2half2_rn(a.x,a.y);
        __half2 h1 = __floats2half2_rn(a.z,a.w);
        __half2 h2 = __floats2half2_rn(b.x,b.y);
        __half2 h3 = __floats2half2_rn(b.z,b.w);
        *(__half2*)&u.x = h0; *(__half2*)&u.y = h1;
        *(__half2*)&u.z = h2; *(__half2*)&u.w = h3;
        *(uint4*)&Bsh[k*PAD + c0] = u;
        float2 g0 = __half22float2(h0), g1 = __half22float2(h1);
        float2 g2 = __half22float2(h2), g3 = __half22float2(h3);
        *(__half2*)&u.x = __floats2half2_rn(a.x-g0.x, a.y-g0.y);
        *(__half2*)&u.y = __floats2half2_rn(a.z-g1.x, a.w-g1.y);
        *(__half2*)&u.z = __floats2half2_rn(b.x-g2.x, b.y-g2.y);
        *(__half2*)&u.w = __floats2half2_rn(b.z-g3.x, b.w-g3.y);
        *(uint4*)&Bsl[k*PAD + c0] = u;
    }
    __syncthreads();

    wmma::fragment<wmma::accumulator, 16,16,16, float> acc[8];
    #pragma unroll
    for (int i = 0; i < 8; i++) wmma::fill_fragment(acc[i], 0.f);

    #pragma unroll
    for (int kk = 0; kk < 4; kk++){
        int ka = kk*16;
        wmma::fragment<wmma::matrix_a, 16,16,16, __half, wmma::row_major> ah, al;
        wmma::load_matrix_sync(ah, Ah + rt*16*PAD + ka, PAD);
        wmma::load_matrix_sync(al, Al + rt*16*PAD + ka, PAD);
        wmma::fragment<wmma::matrix_b, 16,16,16, __half, wmma::row_major> b;
        if (grp == 0){
            #pragma unroll
            for (int ct = 0; ct < 4; ct++){
                wmma::load_matrix_sync(b, Bq + ka*PAD + ct*16, PAD);
                wmma::mma_sync(acc[ct], ah, b, acc[ct]);
                wmma::mma_sync(acc[ct], al, b, acc[ct]);
            }
            #pragma unroll
            for (int ct = 0; ct < 4; ct++){
                wmma::load_matrix_sync(b, Bk + ka*PAD + ct*16, PAD);
                wmma::mma_sync(acc[4+ct], ah, b, acc[4+ct]);
                wmma::mma_sync(acc[4+ct], al, b, acc[4+ct]);
            }
        } else {
            #pragma unroll
            for (int ct = 0; ct < 4; ct++){
                wmma::load_matrix_sync(b, Bv + ka*PAD + ct*16, PAD);
                wmma::mma_sync(acc[ct], ah, b, acc[ct]);
            }
            #pragma unroll
            for (int ct = 0; ct < 4; ct++){
                wmma::load_matrix_sync(b, Bsh + ka*PAD + ct*16, PAD);
                wmma::mma_sync(acc[4+ct], ah, b, acc[4+ct]);
                wmma::mma_sync(acc[4+ct], al, b, acc[4+ct]);
                wmma::load_matrix_sync(b, Bsl + ka*PAD + ct*16, PAD);
                wmma::mma_sync(acc[4+ct], ah, b, acc[4+ct]);
            }
        }
    }
    __syncthreads();

    float* obuf0 = (float*)sm;
    float* obuf1 = (float*)sm + 64*OPAD;
    bool res = (addres != 0);

    // ---- round A: Q (fp16) + V ----
    {
        float* dst = (grp == 0) ? obuf0 : obuf1;
        #pragma unroll
        for (int ct = 0; ct < 4; ct++)
            wmma::store_matrix_sync(dst + rt*16*OPAD + ct*16, acc[ct], OPAD,
                                    wmma::mem_row_major);
    }
    __syncthreads();
    #pragma unroll
    for (int i = 0; i < 4; i++){
        int e = t + i*256;
        int row = e >> 4, c4 = e & 15;
        if (r0 + row < NN){
            size_t grow = (size_t)(r0+row);
            const float* sq = obuf0 + row*OPAD + c4*4;
            float4 bqv = ((const float4*)bq)[c4];
            __half2 q0 = __floats2half2_rn(sq[0]+bqv.x, sq[1]+bqv.y);
            __half2 q1 = __floats2half2_rn(sq[2]+bqv.z, sq[3]+bqv.w);
            uint2 uq; *(__half2*)&uq.x = q0; *(__half2*)&uq.y = q1;
            QH[grow*16 + c4] = uq;
            const float* sv = obuf1 + row*OPAD + c4*4;
            float4 bvv = ((const float4*)bv)[c4];
            __half2 h0 = __floats2half2_rn(sv[0]+bvv.x, sv[1]+bvv.y);
            __half2 h1 = __floats2half2_rn(sv[2]+bvv.z, sv[3]+bvv.w);
            uint2 u; *(__half2*)&u.x = h0; *(__half2*)&u.y = h1;
            ((uint2*)&KV[grow*16 + c4])[1] = u;
        }
    }
    __syncthreads();

    // ---- round B: K + S ----
    {
        float* dst = (grp == 0) ? obuf0 : obuf1;
        #pragma unroll
        for (int ct = 0; ct < 4; ct++)
            wmma::store_matrix_sync(dst + rt*16*OPAD + ct*16, acc[4+ct], OPAD,
                                    wmma::mem_row_major);
    }
    __syncthreads();
    #pragma unroll
    for (int i = 0; i < 4; i++){
        int e = t + i*256;
        int row = e >> 4, c4 = e & 15;
        if (r0 + row < NN){
            size_t grow = (size_t)(r0+row);
            const float* sk_ = obuf0 + row*OPAD + c4*4;
            float4 bkv = ((const float4*)bk)[c4];
            __half2 h0 = __floats2half2_rn(sk_[0]+bkv.x, sk_[1]+bkv.y);
            __half2 h1 = __floats2half2_rn(sk_[2]+bkv.z, sk_[3]+bkv.w);
            uint2 u; *(__half2*)&u.x = h0; *(__half2*)&u.y = h1;
            ((uint2*)&KV[grow*16 + c4])[0] = u;
            const float* ss = obuf1 + row*OPAD + c4*4;
            float4 bsv = ((const float4*)bs)[c4];
            float4 os = make_float4(ss[0]+bsv.x, ss[1]+bsv.y,
                                    ss[2]+bsv.z, ss[3]+bsv.w);
            if (res){
                float4 xv = ((const float4*)X)[grow*16 + c4];
                os.x += xv.x; os.y += xv.y; os.z += xv.z; os.w += xv.w;
            }
            ((float4*)S)[grow*16 + c4] = os;
        }
    }
}

// ------- fused per-node attention, D=64: one node/warp, fp16 q, HFMA2 dots --
__device__ __forceinline__ float dot4hh(__half2 q01, __half2 q23,
                                        unsigned a, unsigned b){
    __half2 p = __hmul2(q01, *(__half2*)&a);
    p = __hfma2(q23, *(__half2*)&b, p);
    float2 f = __half22float2(p);
    return f.x + f.y;
}
__device__ __forceinline__ void accv(float4& acc, float e, unsigned a, unsigned b){
    float2 f01 = __half22float2(*(__half2*)&a);
    float2 f23 = __half22float2(*(__half2*)&b);
    acc.x += e*f01.x; acc.y += e*f01.y; acc.z += e*f23.x; acc.w += e*f23.y;
}

__global__ void __launch_bounds__(256) edge64(int buf, int base, int nnodes){
    int lid = blockIdx.x*8 + (threadIdx.x >> 5);
    if (lid >= nnodes) return;
    int gid = base + lid;
    int lane = threadIdx.x & 15;
    int half = (threadIdx.x >> 4) & 1;
    unsigned gmask = 0xffffu << (threadIdx.x & 16);

    const uint2* QH = g_qh + (size_t)buf*NN*16;
    const float* S  = g_s  + (size_t)buf*NN*64;
    const uint4* KV = g_kvh + (size_t)buf*NN*16;

    uint2 qr = QH[(size_t)gid*16 + lane];
    __half2 q01 = *(__half2*)&qr.x;
    __half2 q23 = *(__half2*)&qr.y;
    int beg = g_ptr[gid], end = g_ptr[gid+1];

    float4 acc = make_float4(0.f,0.f,0.f,0.f);
    float ssum = 0.f;

    for (int i = beg + half*4; i + 4 <= end; i += 8){
        int s0 = g_esrc[i],   s1 = g_esrc[i+1];
        int s2 = g_esrc[i+2], s3 = g_esrc[i+3];
        uint4 kv0 = KV[(size_t)s0*16 + lane];
        uint4 kv1 = KV[(size_t)s1*16 + lane];
        uint4 kv2 = KV[(size_t)s2*16 + lane];
        uint4 kv3 = KV[(size_t)s3*16 + lane];
        float d0 = dot4hh(q01, q23, kv0.x, kv0.y);
        float d1 = dot4hh(q01, q23, kv1.x, kv1.y);
        float d2 = dot4hh(q01, q23, kv2.x, kv2.y);
        float d3 = dot4hh(q01, q23, kv3.x, kv3.y);
        #pragma unroll
        for (int o = 8; o >= 1; o >>= 1){
            d0 += __shfl_xor_sync(gmask, d0, o);
            d1 += __shfl_xor_sync(gmask, d1, o);
            d2 += __shfl_xor_sync(gmask, d2, o);
            d3 += __shfl_xor_sync(gmask, d3, o);
        }
        float e0 = __expf(d0*0.125f);
        float e1 = __expf(d1*0.125f);
        float e2 = __expf(d2*0.125f);
        float e3 = __expf(d3*0.125f);
        ssum += (e0 + e1) + (e2 + e3);
        accv(acc, e0, kv0.z, kv0.w); accv(acc, e1, kv1.z, kv1.w);
        accv(acc, e2, kv2.z, kv2.w); accv(acc, e3, kv3.z, kv3.w);
    }
    if (half == 0){
        for (int i = beg + ((end - beg) & ~3); i < end; i++){
            int s0 = g_esrc[i];
            uint4 kv0 = KV[(size_t)s0*16 + lane];
            float d0 = dot4hh(q01, q23, kv0.x, kv0.y);
            #pragma unroll
            for (int o = 8; o >= 1; o >>= 1)
                d0 += __shfl_xor_sync(gmask, d0, o);
            float e0 = __expf(d0*0.125f);
            ssum += e0;
            accv(acc, e0, kv0.z, kv0.w);
        }
    }
    ssum  += __shfl_xor_sync(0xffffffffu, ssum,  16);
    acc.x += __shfl_xor_sync(0xffffffffu, acc.x, 16);
    acc.y += __shfl_xor_sync(0xffffffffu, acc.y, 16);
    acc.z += __shfl_xor_sync(0xffffffffu, acc.z, 16);
    acc.w += __shfl_xor_sync(0xffffffffu, acc.w, 16);

    float inv = 1.0f / (ssum + 1e-16f);
    float4 sk = ((const float4*)S)[(size_t)gid*16 + lane];
    float4 o;
    o.x = tanhf(acc.x*inv + sk.x);
    o.y = tanhf(acc.y*inv + sk.y);
    o.z = tanhf(acc.z*inv + sk.z);
    o.w = tanhf(acc.w*inv + sk.w);
    if (half == 0)
        ((float4*)g_h)[(size_t)gid*16 + lane] = o;
}

// ---------------- layer 3: 64 -> (3 x 4) GEMM over row range ----------------
__global__ void __launch_bounds__(256) gemm3(
    const float* __restrict__ X,
    const float* __restrict__ Wq, const float* __restrict__ bq,
    const float* __restrict__ Wk, const float* __restrict__ bk,
    const float* __restrict__ Wv, const float* __restrict__ bv,
    const float* __restrict__ Ws, const float* __restrict__ bs,
    const float* __restrict__ noise, int row0)
{
    __shared__ float w[64*12];
    __shared__ float bias[12];
    int t = threadIdx.x;
    if (t < 192){
        int kk = t/3, j = t%3;
        w[kk*12 + 0 + j] = Wq[t];
        w[kk*12 + 3 + j] = Wk[t];
        w[kk*12 + 6 + j] = Wv[t];
        w[kk*12 + 9 + j] = Ws[t];
    }
    if (t < 3){
        bias[t]   = bq[t];
        bias[3+t] = bk[t];
        bias[6+t] = bv[t];
        bias[9+t] = bs[t];
    }
    __syncthreads();
    int node = row0 + blockIdx.x*256 + t;
    if (node >= NN) return;
    float acc[12];
    #pragma unroll
    for (int j = 0; j < 12; j++) acc[j] = 0.f;
    #pragma unroll
    for (int kk = 0; kk < 16; kk++){
        float4 xv = ((const float4*)X)[(size_t)node*16 + kk];
        #pragma unroll
        for (int j = 0; j < 12; j++){
            acc[j] += xv.x * w[(kk*4+0)*12+j]
                    + xv.y * w[(kk*4+1)*12+j]
                    + xv.z * w[(kk*4+2)*12+j]
                    + xv.w * w[(kk*4+3)*12+j];
        }
    }
    float4 q3 = make_float4(acc[0]+bias[0], acc[1]+bias[1], acc[2]+bias[2], 0.f);
    float4 kva = make_float4(acc[3]+bias[3], acc[4]+bias[4], acc[5]+bias[5],
                             acc[6]+bias[6]);
    float4 kvb = make_float4(acc[7]+bias[7], acc[8]+bias[8], 0.f, 0.f);
    float4 s3 = make_float4(acc[9]+bias[9]   + 0.1f*noise[node*3+0],
                            acc[10]+bias[10] + 0.1f*noise[node*3+1],
                            acc[11]+bias[11] + 0.1f*noise[node*3+2], 0.f);
    ((float4*)g_q3)[node] = q3;
    ((float4*)g_kv3)[node*2]   = kva;
    ((float4*)g_kv3)[node*2+1] = kvb;
    ((float4*)g_s3)[node] = s3;
}

// ------- layer-3 per-node attention: 8 lanes per node -------
__global__ void __launch_bounds__(256) edge3(float* __restrict__ out){
    int nid = blockIdx.x*32 + (threadIdx.x >> 3);
    if (nid >= NN) return;
    int lane = threadIdx.x & 7;
    unsigned gmask = 0xFFu << (threadIdx.x & 24);

    float4 q = ((const float4*)g_q3)[nid];
    int beg = g_ptr[nid], end = g_ptr[nid+1];
    float sum = 0.f, ax = 0.f, ay = 0.f, az = 0.f;
    for (int i = beg + lane; i < end; i += 8){
        int s0 = g_esrc[i];
        float4 a0 = ((const float4*)g_kv3)[s0*2];
        float4 b0 = ((const float4*)g_kv3)[s0*2+1];
        float e0 = __expf((q.x*a0.x + q.y*a0.y + q.z*a0.z)*0.57735026919f);
        sum += e0;
        ax += e0*a0.w; ay += e0*b0.x; az += e0*b0.y;
    }
    #pragma unroll
    for (int o = 4; o >= 1; o >>= 1){
        sum += __shfl_xor_sync(gmask, sum, o);
        ax  += __shfl_xor_sync(gmask, ax,  o);
        ay  += __shfl_xor_sync(gmask, ay,  o);
        az  += __shfl_xor_sync(gmask, az,  o);
    }
    if (lane == 0){
        float inv = 1.0f / (sum + 1e-16f);
        float4 s3 = ((const float4*)g_s3)[nid];
        out[nid*3+0] = ax*inv + s3.x;
        out[nid*3+1] = ay*inv + s3.y;
        out[nid*3+2] = az*inv + s3.z;
    }
}

// ---------------- launcher ----------------
extern "C" void kernel_launch(void* const* d_in, const int* in_sizes, int n_in,
                              void* d_out, int out_size)
{
    const float* x     = (const float*)d_in[0];
    const int*   ei    = (const int*)d_in[1];
    const float* noise = (const float*)d_in[2];
    const float* p[24];
    for (int i = 0; i < 24; i++) p[i] = (const float*)d_in[3+i];
    float* out = (float*)d_out;

    float* hptr = nullptr;
    cudaGetSymbolAddress((void**)&hptr, g_h);
    int* degptr = nullptr;
    cudaGetSymbolAddress((void**)&degptr, g_deg);

    static cudaStream_t s2 = nullptr;
    static cudaEvent_t ev_fork = nullptr, ev_csrA = nullptr, ev_csr = nullptr,
                       ev_e1a = nullptr, ev_g2a = nullptr,
                       ev_e2a = nullptr, ev_g3a = nullptr;
    if (!s2){
        cudaStreamCreateWithFlags(&s2, cudaStreamNonBlocking);
        cudaEventCreateWithFlags(&ev_fork, cudaEventDisableTiming);
        cudaEventCreateWithFlags(&ev_csrA, cudaEventDisableTiming);
        cudaEventCreateWithFlags(&ev_csr,  cudaEventDisableTiming);
        cudaEventCreateWithFlags(&ev_e1a,  cudaEventDisableTiming);
        cudaEventCreateWithFlags(&ev_g2a,  cudaEventDisableTiming);
        cudaEventCreateWithFlags(&ev_e2a,  cudaEventDisableTiming);
        cudaEventCreateWithFlags(&ev_g3a,  cudaEventDisableTiming);
        cudaFuncSetAttribute(gemmT, cudaFuncAttributeMaxDynamicSharedMemorySize,
                             SMEM_T);
    }

    int eb4 = (NE/4 + 255)/256;
    const int CH1 = NN - CH0;
    int gg_full = (NN + 63)/64;
    int gg_a = CH0/64;
    int gg_b = (CH1 + 63)/64;
    int ng_a = (CH0 + 7)/8, ng_b = (CH1 + 7)/8;
    int nb3_a = (CH0 + 255)/256, nb3_b = (CH1 + 255)/256;
    int ne3 = (NN + 31)/32;

    // ---- CSR build on side stream (split scatter), overlapped with gemmT1 ----
    cudaEventRecord(ev_fork, 0);
    cudaStreamWaitEvent(s2, ev_fork, 0);
    cudaMemsetAsync(degptr, 0, NN*sizeof(int), s2);
    hist_k<<<eb4,256,0,s2>>>(ei);
    scan_k<<<1,1024,0,s2>>>();
    scatter_k<<<eb4,256,0,s2>>>(ei, 0, CH0);     // edges for edge1a
    cudaEventRecord(ev_csrA, s2);
    scatter_k<<<eb4,256,0,s2>>>(ei, CH0, NN);    // remaining edges (under edge1a)
    cudaEventRecord(ev_csr, s2);

    gemmT<<<gg_full,256,SMEM_T>>>(x, p[0],p[1],p[2],p[3],p[4],p[5],p[6],p[7],
                                  0, 0, 0);

    cudaStreamWaitEvent(0, ev_csrA, 0);
    edge64<<<ng_a,256>>>(0, 0, CH0);
    cudaEventRecord(ev_e1a, 0);
    cudaStreamWaitEvent(0, ev_csr, 0);
    edge64<<<ng_b,256>>>(0, CH0, CH1);

    cudaStreamWaitEvent(s2, ev_e1a, 0);
    gemmT<<<gg_a,256,SMEM_T,s2>>>(hptr, p[8],p[9],p[10],p[11],p[12],p[13],p[14],p[15],
                                  0, 1, 1);
    cudaEventRecord(ev_g2a, s2);

    gemmT<<<gg_b,256,SMEM_T>>>(hptr, p[8],p[9],p[10],p[11],p[12],p[13],p[14],p[15],
                               CH0, 1, 1);
    cudaStreamWaitEvent(0, ev_g2a, 0);

    edge64<<<ng_a,256>>>(1, 0, CH0);
    cudaEventRecord(ev_e2a, 0);
    edge64<<<ng_b,256>>>(1, CH0, CH1);

    cudaStreamWaitEvent(s2, ev_e2a, 0);
    gemm3<<<nb3_a,256,0,s2>>>(hptr, p[16],p[17],p[18],p[19],p[20],p[21],p[22],p[23],
                              noise, 0);
    cudaEventRecord(ev_g3a, s2);

    gemm3<<<nb3_b,256>>>(hptr, p[16],p[17],p[18],p[19],p[20],p[21],p[22],p[23],
                         noise, CH0);
    cudaStreamWaitEvent(0, ev_g3a, 0);
    edge3<<<ne3,256>>>(out);
}